// round 14
// baseline (speedup 1.0000x reference)
#include <cuda_runtime.h>
#include <cuda_fp16.h>
#include <cstdint>

// ---------------- problem constants ----------------
static constexpr int NODES = 1024;
static constexpr int EDGES = 16384;
static constexpr int ETOT  = EDGES + NODES;   // + self loops = 17408
static constexpr int INDIM = 1300;
static constexpr int KPAD1 = 1344;            // INDIM padded to multiple of 64
static constexpr int HEADS = 16;
static constexpr int DHEAD = 512;
static constexpr int HDIM  = HEADS * DHEAD;   // 8192
static constexpr int GROUPS = 8;
static constexpr float SLOPE = 0.2f;

// ---------------- scratch (static device globals; no allocation) ----------------
__device__ __align__(16) float g_bufA[NODES * HDIM];   // GEMM output h
__device__ __align__(16) float g_bufB[NODES * HDIM];   // layer-2 aggregated output
__device__ __align__(16) __half g_xh [NODES * KPAD1];  // x in fp16, K padded
__device__ __align__(16) __half g_w1t[HDIM * KPAD1];   // W1^T fp16 [N,K]
__device__ __align__(16) __half g_w2t[HDIM * HDIM];    // W2^T fp16 [N,K]
__device__ __align__(16) __half g_hh [NODES * HDIM];   // layer-2 input fp16 (aggregate1 out)
__device__ float g_ssrc[NODES * HEADS];
__device__ float g_sdst[NODES * HEADS];
__device__ float g_alpha[ETOT * HEADS];
__device__ int   g_deg[NODES];
__device__ int   g_rp[NODES + 1];
__device__ int   g_cursor[NODES];
__device__ int   g_csr_src[ETOT];
__device__ float g_pooled[GROUPS * HDIM];
__device__ int   g_gstart[GROUPS];
__device__ int   g_gcount[GROUPS];

// ---------------- PTX helpers (arch-portable: ldmatrix / mma.sync / cp.async) ---
__device__ __forceinline__ uint32_t smem_u32(const void* p) {
    uint32_t a;
    asm("{ .reg .u64 t; cvta.to.shared.u64 t, %1; cvt.u32.u64 %0, t; }" : "=r"(a) : "l"(p));
    return a;
}
__device__ __forceinline__ void cp_async16(uint32_t dst, const void* src) {
    asm volatile("cp.async.cg.shared.global [%0], [%1], 16;" :: "r"(dst), "l"(src) : "memory");
}
__device__ __forceinline__ void ldmatrix_x4(uint32_t& r0, uint32_t& r1,
                                            uint32_t& r2, uint32_t& r3, uint32_t addr) {
    asm volatile("ldmatrix.sync.aligned.m8n8.x4.shared.b16 {%0,%1,%2,%3}, [%4];"
                 : "=r"(r0), "=r"(r1), "=r"(r2), "=r"(r3) : "r"(addr));
}
__device__ __forceinline__ void ldmatrix_x2(uint32_t& r0, uint32_t& r1, uint32_t addr) {
    asm volatile("ldmatrix.sync.aligned.m8n8.x2.shared.b16 {%0,%1}, [%2];"
                 : "=r"(r0), "=r"(r1) : "r"(addr));
}
__device__ __forceinline__ void mma16816(float* c, const uint32_t* a, const uint32_t* b) {
    asm volatile("mma.sync.aligned.m16n8k16.row.col.f32.f16.f16.f32 "
                 "{%0,%1,%2,%3}, {%4,%5,%6,%7}, {%8,%9}, {%0,%1,%2,%3};"
                 : "+f"(c[0]), "+f"(c[1]), "+f"(c[2]), "+f"(c[3])
                 : "r"(a[0]), "r"(a[1]), "r"(a[2]), "r"(a[3]), "r"(b[0]), "r"(b[1]));
}

// ---------------- fp16 conversion / transpose ----------------
__global__ void f32_to_f16_pad_kernel(const float* __restrict__ in, __half* __restrict__ out,
                                      int M, int K, int KP) {
    int i = blockIdx.x * blockDim.x + threadIdx.x;  // half2 index over M*KP/2
    if (i >= M * (KP / 2)) return;
    int m = i / (KP / 2), j = i - m * (KP / 2);
    int k = 2 * j;
    __half2 v;
    if (k + 1 < K)
        v = __floats2half2_rn(in[(size_t)m * K + k], in[(size_t)m * K + k + 1]);
    else
        v = __floats2half2_rn(0.f, 0.f);
    ((__half2*)out)[i] = v;
}

// out[n*KP + k] fp16 = in[k*N + n]; zero-pad k >= K. N % 32 == 0, KP % 32 == 0.
__global__ void transpose_f16_kernel(const float* __restrict__ in, __half* __restrict__ out,
                                     int K, int Nn, int KP) {
    __shared__ float t[32][33];
    int kBase = blockIdx.y * 32, nBase = blockIdx.x * 32;
    int tx = threadIdx.x, ty = threadIdx.y;   // (32, 8)
#pragma unroll
    for (int j = 0; j < 32; j += 8) {
        int k = kBase + ty + j;
        t[ty + j][tx] = (k < K) ? in[(size_t)k * Nn + nBase + tx] : 0.f;
    }
    __syncthreads();
#pragma unroll
    for (int j = 0; j < 32; j += 8) {
        int n = nBase + ty + j;
        out[(size_t)n * KP + kBase + tx] = __float2half_rn(t[tx][ty + j]);
    }
}

// ---------------- HMMA GEMM: C[M,N] fp32 = A[M,K]fp16 * Bt[N,K]fp16^T -----------
// 128x128 block tile, BK=32, 256 threads, 8 warps * (64x32) via m16n8k16.
// Double-buffered cp.async, ONE __syncthreads per K-iter.
static constexpr int SPAD = 40;

__global__ __launch_bounds__(256) void gemm_hmma_kernel(
    const __half* __restrict__ A, const __half* __restrict__ B,
    float* __restrict__ C, int K, int Nn)
{
    __shared__ __align__(16) __half As[2][128][SPAD];
    __shared__ __align__(16) __half Bs[2][128][SPAD];

    const int tid  = threadIdx.x;
    const int lane = tid & 31, wid = tid >> 5;
    const int wm = (wid & 1) * 64;          // warp M offset in tile
    const int wn = (wid >> 1) * 32;         // warp N offset in tile
    const int rowBase = blockIdx.y * 128;
    const int colBase = blockIdx.x * 128;

    const __half* gA = A + (size_t)rowBase * K;
    const __half* gB = B + (size_t)colBase * K;

    const int ldCol = (tid & 3) * 8;        // halves within BK=32
    const int ldRow = tid >> 2;             // 0..63 (+64 for second chunk)

    float acc[4][4][4];
#pragma unroll
    for (int mi = 0; mi < 4; mi++)
#pragma unroll
        for (int ni = 0; ni < 4; ni++)
#pragma unroll
            for (int j = 0; j < 4; j++) acc[mi][ni][j] = 0.f;

    // prologue: stage tile 0 into buffer 0
#pragma unroll
    for (int i = 0; i < 2; i++) {
        int row = ldRow + i * 64;
        cp_async16(smem_u32(&As[0][row][ldCol]), gA + (size_t)row * K + ldCol);
        cp_async16(smem_u32(&Bs[0][row][ldCol]), gB + (size_t)row * K + ldCol);
    }
    asm volatile("cp.async.commit_group;" ::: "memory");

    const int T = K >> 5;
    for (int t = 0; t < T; t++) {
        const int buf = t & 1;
        asm volatile("cp.async.wait_group 0;" ::: "memory");
        __syncthreads();                         // tile t visible to all warps
        // Stage tile t+1 into nbuf. nbuf was last READ during compute of t-1,
        // which every warp finished before the barrier above.
        if (t + 1 < T) {
            const int nbuf = buf ^ 1, k0 = (t + 1) << 5;
#pragma unroll
            for (int i = 0; i < 2; i++) {
                int row = ldRow + i * 64;
                cp_async16(smem_u32(&As[nbuf][row][ldCol]), gA + (size_t)row * K + k0 + ldCol);
                cp_async16(smem_u32(&Bs[nbuf][row][ldCol]), gB + (size_t)row * K + k0 + ldCol);
            }
            asm volatile("cp.async.commit_group;" ::: "memory");
        }

#pragma unroll
        for (int kk = 0; kk < 32; kk += 16) {
            uint32_t af[4][4], bf[4][2];
#pragma unroll
            for (int mi = 0; mi < 4; mi++) {
                uint32_t addr = smem_u32(
                    &As[buf][wm + mi * 16 + (lane & 15)][kk + (lane >> 4) * 8]);
                ldmatrix_x4(af[mi][0], af[mi][1], af[mi][2], af[mi][3], addr);
            }
#pragma unroll
            for (int ni = 0; ni < 4; ni++) {
                int l16 = lane & 15;
                uint32_t addr = smem_u32(
                    &Bs[buf][wn + ni * 8 + (l16 & 7)][kk + (l16 >> 3) * 8]);
                ldmatrix_x2(bf[ni][0], bf[ni][1], addr);
            }
#pragma unroll
            for (int mi = 0; mi < 4; mi++)
#pragma unroll
                for (int ni = 0; ni < 4; ni++)
                    mma16816(acc[mi][ni], af[mi], bf[ni]);
        }
    }

    // epilogue: c0,c1 at (row = lane>>2, col = 2*(lane&3)), c2,c3 at row+8
#pragma unroll
    for (int mi = 0; mi < 4; mi++) {
        int r0 = rowBase + wm + mi * 16 + (lane >> 2);
#pragma unroll
        for (int ni = 0; ni < 4; ni++) {
            int c0 = colBase + wn + ni * 8 + (lane & 3) * 2;
            *(float2*)&C[(size_t)r0 * Nn + c0]       = make_float2(acc[mi][ni][0], acc[mi][ni][1]);
            *(float2*)&C[(size_t)(r0 + 8) * Nn + c0] = make_float2(acc[mi][ni][2], acc[mi][ni][3]);
        }
    }
}

// ---------------- CSR build (dst-grouped) ----------------
__global__ void zero_meta_kernel() {
    int i = blockIdx.x * blockDim.x + threadIdx.x;
    if (i < NODES) g_deg[i] = 0;
    if (i < GROUPS) { g_gcount[i] = 0; g_gstart[i] = 0; }
}
__global__ void deg_kernel(const int* __restrict__ ei) {
    int k = blockIdx.x * blockDim.x + threadIdx.x;
    if (k >= ETOT) return;
    int dst = (k < EDGES) ? ei[EDGES + k] : (k - EDGES);
    atomicAdd(&g_deg[dst], 1);
}
__global__ void scan_kernel() {
    __shared__ int s[NODES];
    int t = threadIdx.x;
    int d = g_deg[t];
    s[t] = d;
    __syncthreads();
    for (int o = 1; o < NODES; o <<= 1) {
        int v = (t >= o) ? s[t - o] : 0;
        __syncthreads();
        s[t] += v;
        __syncthreads();
    }
    if (t == 0) g_rp[0] = 0;
    g_rp[t + 1] = s[t];
    g_cursor[t] = s[t] - d;
}
__global__ void fill_csr_kernel(const int* __restrict__ ei) {
    int k = blockIdx.x * blockDim.x + threadIdx.x;
    if (k >= ETOT) return;
    int src, dst;
    if (k < EDGES) { src = ei[k]; dst = ei[EDGES + k]; }
    else           { src = dst = k - EDGES; }
    int pos = atomicAdd(&g_cursor[dst], 1);
    g_csr_src[pos] = src;
}

// ---------------- attention ----------------
__global__ void scores_kernel(const float* __restrict__ h,
                              const float* __restrict__ a_src,
                              const float* __restrict__ a_dst) {
    int warpId = (blockIdx.x * blockDim.x + threadIdx.x) >> 5;
    int lane = threadIdx.x & 31;
    if (warpId >= NODES * HEADS) return;
    int n = warpId / HEADS, hh = warpId % HEADS;
    const float* hp  = h + (size_t)n * HDIM + hh * DHEAD;
    const float* asp = a_src + hh * DHEAD;
    const float* adp = a_dst + hh * DHEAD;
    float ss = 0.f, sd = 0.f;
    for (int d = lane; d < DHEAD; d += 32) {
        float v = hp[d];
        ss += v * asp[d];
        sd += v * adp[d];
    }
#pragma unroll
    for (int o = 16; o; o >>= 1) {
        ss += __shfl_xor_sync(0xffffffffu, ss, o);
        sd += __shfl_xor_sync(0xffffffffu, sd, o);
    }
    if (lane == 0) {
        g_ssrc[n * HEADS + hh] = ss;
        g_sdst[n * HEADS + hh] = sd;
    }
}

__global__ void attn_kernel() {
    int t = blockIdx.x * blockDim.x + threadIdx.x;
    if (t >= NODES * HEADS) return;
    int hh = t % HEADS, n = t / HEADS;
    float sd = g_sdst[n * HEADS + hh];
    int b = g_rp[n], e = g_rp[n + 1];
    float m = -1e30f;
    for (int i = b; i < e; i++) {
        float x = g_ssrc[g_csr_src[i] * HEADS + hh] + sd;
        x = (x > 0.f) ? x : SLOPE * x;
        m = fmaxf(m, x);
    }
    float sum = 0.f;
    for (int i = b; i < e; i++) {
        float x = g_ssrc[g_csr_src[i] * HEADS + hh] + sd;
        x = (x > 0.f) ? x : SLOPE * x;
        float p = __expf(x - m);
        sum += p;
        g_alpha[i * HEADS + hh] = p;
    }
    float inv = 1.f / sum;
    for (int i = b; i < e; i++) g_alpha[i * HEADS + hh] *= inv;
}

// out[n,f] = relu( sum_{edges into n} alpha * h[src,f] + bias[f] )
// 4x unrolled edge loop (4 independent gather chains -> MLP 4 on L2 hits).
// OutT = __half (layer 1, feeds GEMM2 A) or float (layer 2, feeds pooling).
template <typename OutT>
__global__ void aggregate_kernel(const float* __restrict__ h,
                                 const float* __restrict__ bias,
                                 OutT* __restrict__ out) {
    int t = blockIdx.x * blockDim.x + threadIdx.x;
    if (t >= NODES * (HDIM / 4)) return;
    int f4 = t & (HDIM / 4 - 1);
    int n  = t >> 11;
    int hh = f4 >> 7;
    int b = g_rp[n], e = g_rp[n + 1];
    float4 acc = make_float4(0.f, 0.f, 0.f, 0.f);

    int i = b;
    for (; i + 4 <= e; i += 4) {
        int s0 = g_csr_src[i],     s1 = g_csr_src[i + 1];
        int s2 = g_csr_src[i + 2], s3 = g_csr_src[i + 3];
        float a0 = __ldg(&g_alpha[(i    ) * HEADS + hh]);
        float a1 = __ldg(&g_alpha[(i + 1) * HEADS + hh]);
        float a2 = __ldg(&g_alpha[(i + 2) * HEADS + hh]);
        float a3 = __ldg(&g_alpha[(i + 3) * HEADS + hh]);
        float4 v0 = *(const float4*)&h[(size_t)s0 * HDIM + f4 * 4];
        float4 v1 = *(const float4*)&h[(size_t)s1 * HDIM + f4 * 4];
        float4 v2 = *(const float4*)&h[(size_t)s2 * HDIM + f4 * 4];
        float4 v3 = *(const float4*)&h[(size_t)s3 * HDIM + f4 * 4];
        acc.x += a0 * v0.x + a1 * v1.x + a2 * v2.x + a3 * v3.x;
        acc.y += a0 * v0.y + a1 * v1.y + a2 * v2.y + a3 * v3.y;
        acc.z += a0 * v0.z + a1 * v1.z + a2 * v2.z + a3 * v3.z;
        acc.w += a0 * v0.w + a1 * v1.w + a2 * v2.w + a3 * v3.w;
    }
    for (; i < e; i++) {
        float a = __ldg(&g_alpha[i * HEADS + hh]);
        float4 v = *(const float4*)&h[(size_t)g_csr_src[i] * HDIM + f4 * 4];
        acc.x += a * v.x; acc.y += a * v.y; acc.z += a * v.z; acc.w += a * v.w;
    }

    float4 bb = *(const float4*)&bias[f4 * 4];
    acc.x = fmaxf(acc.x + bb.x, 0.f);
    acc.y = fmaxf(acc.y + bb.y, 0.f);
    acc.z = fmaxf(acc.z + bb.z, 0.f);
    acc.w = fmaxf(acc.w + bb.w, 0.f);

    if constexpr (sizeof(OutT) == 2) {
        __half2 lo = __floats2half2_rn(acc.x, acc.y);
        __half2 hi = __floats2half2_rn(acc.z, acc.w);
        __half2* op = (__half2*)&out[(size_t)n * HDIM + f4 * 4];
        op[0] = lo; op[1] = hi;
    } else {
        *(float4*)&out[(size_t)n * HDIM + f4 * 4] = acc;
    }
}

// ---------------- pooling + classifier ----------------
__global__ void group_bounds_kernel(const int* __restrict__ batch) {
    int n = blockIdx.x * blockDim.x + threadIdx.x;
    if (n >= NODES) return;
    int g = batch[n];
    atomicAdd(&g_gcount[g], 1);
    if (n == 0 || batch[n - 1] != g) g_gstart[g] = n;
}
__global__ void pool_kernel(const float* __restrict__ h) {
    int t = blockIdx.x * blockDim.x + threadIdx.x;
    if (t >= GROUPS * (HDIM / 4)) return;
    int f4 = t & (HDIM / 4 - 1);
    int g  = t >> 11;
    int s = g_gstart[g], c = g_gcount[g];
    float4 acc = make_float4(0.f, 0.f, 0.f, 0.f);
    for (int i = 0; i < c; i++) {
        float4 v = *(const float4*)&h[(size_t)(s + i) * HDIM + f4 * 4];
        acc.x += v.x; acc.y += v.y; acc.z += v.z; acc.w += v.w;
    }
    float inv = (c > 0) ? (1.f / (float)c) : 0.f;
    acc.x *= inv; acc.y *= inv; acc.z *= inv; acc.w *= inv;
    *(float4*)&g_pooled[(size_t)g * HDIM + f4 * 4] = acc;
}
__global__ void final_kernel(const float* __restrict__ lw,
                             const float* __restrict__ lb,
                             float* __restrict__ out) {
    __shared__ float red[256];
    int g = blockIdx.x;
    float s = 0.f;
    for (int f = threadIdx.x; f < HDIM; f += 256)
        s += g_pooled[(size_t)g * HDIM + f] * lw[f];
    red[threadIdx.x] = s;
    __syncthreads();
    for (int o = 128; o; o >>= 1) {
        if (threadIdx.x < o) red[threadIdx.x] += red[threadIdx.x + o];
        __syncthreads();
    }
    if (threadIdx.x == 0) out[g] = red[0] + lb[0];
}

// ---------------- launch ----------------
extern "C" void kernel_launch(void* const* d_in, const int* in_sizes, int n_in,
                              void* d_out, int out_size) {
    const float* x   = (const float*)d_in[0];
    const int*   ei  = (const int*)  d_in[1];
    const int*   bat = (const int*)  d_in[2];
    const float* W1  = (const float*)d_in[3];
    const float* as1 = (const float*)d_in[4];
    const float* ad1 = (const float*)d_in[5];
    const float* b1  = (const float*)d_in[6];
    const float* W2  = (const float*)d_in[7];
    const float* as2 = (const float*)d_in[8];
    const float* ad2 = (const float*)d_in[9];
    const float* b2  = (const float*)d_in[10];
    const float* lw  = (const float*)d_in[11];
    const float* lb  = (const float*)d_in[12];
    float* out = (float*)d_out;

    float *bufA, *bufB;
    __half *xh, *w1t, *w2t, *hh;
    cudaGetSymbolAddress((void**)&bufA, g_bufA);
    cudaGetSymbolAddress((void**)&bufB, g_bufB);
    cudaGetSymbolAddress((void**)&xh,  g_xh);
    cudaGetSymbolAddress((void**)&w1t, g_w1t);
    cudaGetSymbolAddress((void**)&w2t, g_w2t);
    cudaGetSymbolAddress((void**)&hh,  g_hh);

    const int TB = 256;
    const int edgeBlocks = (ETOT + TB - 1) / TB;

    // CSR build
    zero_meta_kernel<<<(NODES + TB - 1) / TB, TB>>>();
    deg_kernel<<<edgeBlocks, TB>>>(ei);
    scan_kernel<<<1, NODES>>>();
    fill_csr_kernel<<<edgeBlocks, TB>>>(ei);

    // fp16 conversions (weights + layer-1 input)
    f32_to_f16_pad_kernel<<<(NODES * KPAD1 / 2 + TB - 1) / TB, TB>>>(x, xh, NODES, INDIM, KPAD1);
    transpose_f16_kernel<<<dim3(HDIM / 32, KPAD1 / 32), dim3(32, 8)>>>(W1, w1t, INDIM, HDIM, KPAD1);
    transpose_f16_kernel<<<dim3(HDIM / 32, HDIM / 32), dim3(32, 8)>>>(W2, w2t, HDIM, HDIM, HDIM);

    dim3 gemmGrid(HDIM / 128, NODES / 128);   // (64, 8)
    const int aggBlocks   = NODES * (HDIM / 4) / TB;
    const int scoreBlocks = (NODES * HEADS * 32 + TB - 1) / TB;
    const int attnBlocks  = (NODES * HEADS + TB - 1) / TB;

    // ---- layer 1 ----
    gemm_hmma_kernel<<<gemmGrid, TB>>>(xh, w1t, bufA, KPAD1, HDIM);
    scores_kernel<<<scoreBlocks, TB>>>(bufA, as1, ad1);
    attn_kernel<<<attnBlocks, TB>>>();
    aggregate_kernel<__half><<<aggBlocks, TB>>>(bufA, b1, hh);   // fp16 out -> GEMM2 A

    // ---- layer 2 ----
    gemm_hmma_kernel<<<gemmGrid, TB>>>(hh, w2t, bufA, HDIM, HDIM);
    scores_kernel<<<scoreBlocks, TB>>>(bufA, as2, ad2);
    attn_kernel<<<attnBlocks, TB>>>();
    aggregate_kernel<float><<<aggBlocks, TB>>>(bufA, b2, bufB);

    // ---- pooling + classifier ----
    group_bounds_kernel<<<(NODES + TB - 1) / TB, TB>>>(bat);
    pool_kernel<<<GROUPS * (HDIM / 4) / TB, TB>>>(bufB);
    final_kernel<<<GROUPS, TB>>>(lw, lb, out);
}

// round 15
// speedup vs baseline: 1.0695x; 1.0695x over previous
#include <cuda_runtime.h>
#include <cuda_fp16.h>
#include <cstdint>

// ---------------- problem constants ----------------
static constexpr int NODES = 1024;
static constexpr int EDGES = 16384;
static constexpr int ETOT  = EDGES + NODES;   // + self loops = 17408
static constexpr int INDIM = 1300;
static constexpr int KPAD1 = 1344;            // INDIM padded to multiple of 64
static constexpr int HEADS = 16;
static constexpr int DHEAD = 512;
static constexpr int HDIM  = HEADS * DHEAD;   // 8192
static constexpr int GROUPS = 8;
static constexpr float SLOPE = 0.2f;

// ---------------- scratch (static device globals; no allocation) ----------------
__device__ __align__(16) float g_bufA[NODES * HDIM];   // GEMM output h
__device__ __align__(16) float g_bufB[NODES * HDIM];   // layer-2 aggregated output
__device__ __align__(16) __half g_xh [NODES * KPAD1];  // x in fp16, K padded
__device__ __align__(16) __half g_w1t[HDIM * KPAD1];   // W1^T fp16 [N,K]
__device__ __align__(16) __half g_w2t[HDIM * HDIM];    // W2^T fp16 [N,K]
__device__ __align__(16) __half g_hh [NODES * HDIM];   // layer-2 input fp16 (aggregate1 out)
__device__ float g_ssrc[NODES * HEADS];
__device__ float g_sdst[NODES * HEADS];
__device__ float g_alpha[ETOT * HEADS];
__device__ int   g_deg[NODES];
__device__ int   g_rp[NODES + 1];
__device__ int   g_cursor[NODES];
__device__ int   g_csr_src[ETOT];
__device__ float g_pooled[GROUPS * HDIM];
__device__ int   g_gstart[GROUPS];
__device__ int   g_gcount[GROUPS];

// ---------------- PTX helpers (arch-portable: ldmatrix / mma.sync / cp.async) ---
__device__ __forceinline__ uint32_t smem_u32(const void* p) {
    uint32_t a;
    asm("{ .reg .u64 t; cvta.to.shared.u64 t, %1; cvt.u32.u64 %0, t; }" : "=r"(a) : "l"(p));
    return a;
}
__device__ __forceinline__ void cp_async16(uint32_t dst, const void* src) {
    asm volatile("cp.async.cg.shared.global [%0], [%1], 16;" :: "r"(dst), "l"(src) : "memory");
}
__device__ __forceinline__ void ldmatrix_x4(uint32_t& r0, uint32_t& r1,
                                            uint32_t& r2, uint32_t& r3, uint32_t addr) {
    asm volatile("ldmatrix.sync.aligned.m8n8.x4.shared.b16 {%0,%1,%2,%3}, [%4];"
                 : "=r"(r0), "=r"(r1), "=r"(r2), "=r"(r3) : "r"(addr));
}
__device__ __forceinline__ void ldmatrix_x2(uint32_t& r0, uint32_t& r1, uint32_t addr) {
    asm volatile("ldmatrix.sync.aligned.m8n8.x2.shared.b16 {%0,%1}, [%2];"
                 : "=r"(r0), "=r"(r1) : "r"(addr));
}
__device__ __forceinline__ void mma16816(float* c, const uint32_t* a, const uint32_t* b) {
    asm volatile("mma.sync.aligned.m16n8k16.row.col.f32.f16.f16.f32 "
                 "{%0,%1,%2,%3}, {%4,%5,%6,%7}, {%8,%9}, {%0,%1,%2,%3};"
                 : "+f"(c[0]), "+f"(c[1]), "+f"(c[2]), "+f"(c[3])
                 : "r"(a[0]), "r"(a[1]), "r"(a[2]), "r"(a[3]), "r"(b[0]), "r"(b[1]));
}

// ---------------- fp16 conversion / transpose ----------------
__global__ void f32_to_f16_pad_kernel(const float* __restrict__ in, __half* __restrict__ out,
                                      int M, int K, int KP) {
    int i = blockIdx.x * blockDim.x + threadIdx.x;  // half2 index over M*KP/2
    if (i >= M * (KP / 2)) return;
    int m = i / (KP / 2), j = i - m * (KP / 2);
    int k = 2 * j;
    __half2 v;
    if (k + 1 < K)
        v = __floats2half2_rn(in[(size_t)m * K + k], in[(size_t)m * K + k + 1]);
    else
        v = __floats2half2_rn(0.f, 0.f);
    ((__half2*)out)[i] = v;
}

// out[n*KP + k] fp16 = in[k*N + n]; zero-pad k >= K. N % 32 == 0, KP % 32 == 0.
__global__ void transpose_f16_kernel(const float* __restrict__ in, __half* __restrict__ out,
                                     int K, int Nn, int KP) {
    __shared__ float t[32][33];
    int kBase = blockIdx.y * 32, nBase = blockIdx.x * 32;
    int tx = threadIdx.x, ty = threadIdx.y;   // (32, 8)
#pragma unroll
    for (int j = 0; j < 32; j += 8) {
        int k = kBase + ty + j;
        t[ty + j][tx] = (k < K) ? in[(size_t)k * Nn + nBase + tx] : 0.f;
    }
    __syncthreads();
#pragma unroll
    for (int j = 0; j < 32; j += 8) {
        int n = nBase + ty + j;
        out[(size_t)n * KP + kBase + tx] = __float2half_rn(t[tx][ty + j]);
    }
}

// ---------------- HMMA GEMM: C[M,N] fp32 = A[M,K]fp16 * Bt[N,K]fp16^T -----------
// 128x128 block tile, BK=32, 256 threads, 8 warps * (64x32) via m16n8k16.
// R13 pipeline structure: prefetch issued first, wait_group 1, two barriers/iter.
static constexpr int SPAD = 40;

__global__ __launch_bounds__(256) void gemm_hmma_kernel(
    const __half* __restrict__ A, const __half* __restrict__ B,
    float* __restrict__ C, int K, int Nn)
{
    __shared__ __align__(16) __half As[2][128][SPAD];
    __shared__ __align__(16) __half Bs[2][128][SPAD];

    const int tid  = threadIdx.x;
    const int lane = tid & 31, wid = tid >> 5;
    const int wm = (wid & 1) * 64;          // warp M offset in tile
    const int wn = (wid >> 1) * 32;         // warp N offset in tile
    const int rowBase = blockIdx.y * 128;
    const int colBase = blockIdx.x * 128;

    const __half* gA = A + (size_t)rowBase * K;
    const __half* gB = B + (size_t)colBase * K;

    const int ldCol = (tid & 3) * 8;        // halves within BK=32
    const int ldRow = tid >> 2;             // 0..63 (+64 for second chunk)

    float acc[4][4][4];
#pragma unroll
    for (int mi = 0; mi < 4; mi++)
#pragma unroll
        for (int ni = 0; ni < 4; ni++)
#pragma unroll
            for (int j = 0; j < 4; j++) acc[mi][ni][j] = 0.f;

    // prologue: load tile 0
#pragma unroll
    for (int i = 0; i < 2; i++) {
        int row = ldRow + i * 64;
        cp_async16(smem_u32(&As[0][row][ldCol]), gA + (size_t)row * K + ldCol);
        cp_async16(smem_u32(&Bs[0][row][ldCol]), gB + (size_t)row * K + ldCol);
    }
    asm volatile("cp.async.commit_group;" ::: "memory");

    const int T = K >> 5;
    for (int t = 0; t < T; t++) {
        const int buf = t & 1;
        if (t + 1 < T) {
            const int nbuf = buf ^ 1, k0 = (t + 1) << 5;
#pragma unroll
            for (int i = 0; i < 2; i++) {
                int row = ldRow + i * 64;
                cp_async16(smem_u32(&As[nbuf][row][ldCol]), gA + (size_t)row * K + k0 + ldCol);
                cp_async16(smem_u32(&Bs[nbuf][row][ldCol]), gB + (size_t)row * K + k0 + ldCol);
            }
            asm volatile("cp.async.commit_group;" ::: "memory");
            asm volatile("cp.async.wait_group 1;" ::: "memory");
        } else {
            asm volatile("cp.async.wait_group 0;" ::: "memory");
        }
        __syncthreads();   // tile t resident

#pragma unroll
        for (int kk = 0; kk < 32; kk += 16) {
            uint32_t af[4][4], bf[4][2];
#pragma unroll
            for (int mi = 0; mi < 4; mi++) {
                uint32_t addr = smem_u32(
                    &As[buf][wm + mi * 16 + (lane & 15)][kk + (lane >> 4) * 8]);
                ldmatrix_x4(af[mi][0], af[mi][1], af[mi][2], af[mi][3], addr);
            }
#pragma unroll
            for (int ni = 0; ni < 4; ni++) {
                int l16 = lane & 15;
                uint32_t addr = smem_u32(
                    &Bs[buf][wn + ni * 8 + (l16 & 7)][kk + (l16 >> 3) * 8]);
                ldmatrix_x2(bf[ni][0], bf[ni][1], addr);
            }
#pragma unroll
            for (int mi = 0; mi < 4; mi++)
#pragma unroll
                for (int ni = 0; ni < 4; ni++)
                    mma16816(acc[mi][ni], af[mi], bf[ni]);
        }
        __syncthreads();   // compute done before buf is overwritten at t+2
    }

    // epilogue: c0,c1 at (row = lane>>2, col = 2*(lane&3)), c2,c3 at row+8
#pragma unroll
    for (int mi = 0; mi < 4; mi++) {
        int r0 = rowBase + wm + mi * 16 + (lane >> 2);
#pragma unroll
        for (int ni = 0; ni < 4; ni++) {
            int c0 = colBase + wn + ni * 8 + (lane & 3) * 2;
            *(float2*)&C[(size_t)r0 * Nn + c0]       = make_float2(acc[mi][ni][0], acc[mi][ni][1]);
            *(float2*)&C[(size_t)(r0 + 8) * Nn + c0] = make_float2(acc[mi][ni][2], acc[mi][ni][3]);
        }
    }
}

// ---------------- CSR build (dst-grouped) ----------------
__global__ void zero_meta_kernel() {
    int i = blockIdx.x * blockDim.x + threadIdx.x;
    if (i < NODES) g_deg[i] = 0;
    if (i < GROUPS) { g_gcount[i] = 0; g_gstart[i] = 0; }
}
__global__ void deg_kernel(const int* __restrict__ ei) {
    int k = blockIdx.x * blockDim.x + threadIdx.x;
    if (k >= ETOT) return;
    int dst = (k < EDGES) ? ei[EDGES + k] : (k - EDGES);
    atomicAdd(&g_deg[dst], 1);
}
__global__ void scan_kernel() {
    __shared__ int s[NODES];
    int t = threadIdx.x;
    int d = g_deg[t];
    s[t] = d;
    __syncthreads();
    for (int o = 1; o < NODES; o <<= 1) {
        int v = (t >= o) ? s[t - o] : 0;
        __syncthreads();
        s[t] += v;
        __syncthreads();
    }
    if (t == 0) g_rp[0] = 0;
    g_rp[t + 1] = s[t];
    g_cursor[t] = s[t] - d;
}
__global__ void fill_csr_kernel(const int* __restrict__ ei) {
    int k = blockIdx.x * blockDim.x + threadIdx.x;
    if (k >= ETOT) return;
    int src, dst;
    if (k < EDGES) { src = ei[k]; dst = ei[EDGES + k]; }
    else           { src = dst = k - EDGES; }
    int pos = atomicAdd(&g_cursor[dst], 1);
    g_csr_src[pos] = src;
}

// ---------------- attention ----------------
__global__ void scores_kernel(const float* __restrict__ h,
                              const float* __restrict__ a_src,
                              const float* __restrict__ a_dst) {
    int warpId = (blockIdx.x * blockDim.x + threadIdx.x) >> 5;
    int lane = threadIdx.x & 31;
    if (warpId >= NODES * HEADS) return;
    int n = warpId / HEADS, hh = warpId % HEADS;
    const float* hp  = h + (size_t)n * HDIM + hh * DHEAD;
    const float* asp = a_src + hh * DHEAD;
    const float* adp = a_dst + hh * DHEAD;
    float ss = 0.f, sd = 0.f;
    for (int d = lane; d < DHEAD; d += 32) {
        float v = hp[d];
        ss += v * asp[d];
        sd += v * adp[d];
    }
#pragma unroll
    for (int o = 16; o; o >>= 1) {
        ss += __shfl_xor_sync(0xffffffffu, ss, o);
        sd += __shfl_xor_sync(0xffffffffu, sd, o);
    }
    if (lane == 0) {
        g_ssrc[n * HEADS + hh] = ss;
        g_sdst[n * HEADS + hh] = sd;
    }
}

__global__ void attn_kernel() {
    int t = blockIdx.x * blockDim.x + threadIdx.x;
    if (t >= NODES * HEADS) return;
    int hh = t % HEADS, n = t / HEADS;
    float sd = g_sdst[n * HEADS + hh];
    int b = g_rp[n], e = g_rp[n + 1];
    float m = -1e30f;
    for (int i = b; i < e; i++) {
        float x = g_ssrc[g_csr_src[i] * HEADS + hh] + sd;
        x = (x > 0.f) ? x : SLOPE * x;
        m = fmaxf(m, x);
    }
    float sum = 0.f;
    for (int i = b; i < e; i++) {
        float x = g_ssrc[g_csr_src[i] * HEADS + hh] + sd;
        x = (x > 0.f) ? x : SLOPE * x;
        float p = __expf(x - m);
        sum += p;
        g_alpha[i * HEADS + hh] = p;
    }
    float inv = 1.f / sum;
    for (int i = b; i < e; i++) g_alpha[i * HEADS + hh] *= inv;
}

// out[n,f] = relu( sum_{edges into n} alpha * h[src,f] + bias[f] )
// 4x unrolled edge loop (4 independent gather chains -> MLP 4 on L2 hits).
// OutT = __half (layer 1, feeds GEMM2 A) or float (layer 2, feeds pooling).
template <typename OutT>
__global__ void aggregate_kernel(const float* __restrict__ h,
                                 const float* __restrict__ bias,
                                 OutT* __restrict__ out) {
    int t = blockIdx.x * blockDim.x + threadIdx.x;
    if (t >= NODES * (HDIM / 4)) return;
    int f4 = t & (HDIM / 4 - 1);
    int n  = t >> 11;
    int hh = f4 >> 7;
    int b = g_rp[n], e = g_rp[n + 1];
    float4 acc = make_float4(0.f, 0.f, 0.f, 0.f);

    int i = b;
    for (; i + 4 <= e; i += 4) {
        int s0 = g_csr_src[i],     s1 = g_csr_src[i + 1];
        int s2 = g_csr_src[i + 2], s3 = g_csr_src[i + 3];
        float a0 = __ldg(&g_alpha[(i    ) * HEADS + hh]);
        float a1 = __ldg(&g_alpha[(i + 1) * HEADS + hh]);
        float a2 = __ldg(&g_alpha[(i + 2) * HEADS + hh]);
        float a3 = __ldg(&g_alpha[(i + 3) * HEADS + hh]);
        float4 v0 = *(const float4*)&h[(size_t)s0 * HDIM + f4 * 4];
        float4 v1 = *(const float4*)&h[(size_t)s1 * HDIM + f4 * 4];
        float4 v2 = *(const float4*)&h[(size_t)s2 * HDIM + f4 * 4];
        float4 v3 = *(const float4*)&h[(size_t)s3 * HDIM + f4 * 4];
        acc.x += a0 * v0.x + a1 * v1.x + a2 * v2.x + a3 * v3.x;
        acc.y += a0 * v0.y + a1 * v1.y + a2 * v2.y + a3 * v3.y;
        acc.z += a0 * v0.z + a1 * v1.z + a2 * v2.z + a3 * v3.z;
        acc.w += a0 * v0.w + a1 * v1.w + a2 * v2.w + a3 * v3.w;
    }
    for (; i < e; i++) {
        float a = __ldg(&g_alpha[i * HEADS + hh]);
        float4 v = *(const float4*)&h[(size_t)g_csr_src[i] * HDIM + f4 * 4];
        acc.x += a * v.x; acc.y += a * v.y; acc.z += a * v.z; acc.w += a * v.w;
    }

    float4 bb = *(const float4*)&bias[f4 * 4];
    acc.x = fmaxf(acc.x + bb.x, 0.f);
    acc.y = fmaxf(acc.y + bb.y, 0.f);
    acc.z = fmaxf(acc.z + bb.z, 0.f);
    acc.w = fmaxf(acc.w + bb.w, 0.f);

    if constexpr (sizeof(OutT) == 2) {
        __half2 lo = __floats2half2_rn(acc.x, acc.y);
        __half2 hi = __floats2half2_rn(acc.z, acc.w);
        __half2* op = (__half2*)&out[(size_t)n * HDIM + f4 * 4];
        op[0] = lo; op[1] = hi;
    } else {
        *(float4*)&out[(size_t)n * HDIM + f4 * 4] = acc;
    }
}

// ---------------- pooling + classifier ----------------
__global__ void group_bounds_kernel(const int* __restrict__ batch) {
    int n = blockIdx.x * blockDim.x + threadIdx.x;
    if (n >= NODES) return;
    int g = batch[n];
    atomicAdd(&g_gcount[g], 1);
    if (n == 0 || batch[n - 1] != g) g_gstart[g] = n;
}
__global__ void pool_kernel(const float* __restrict__ h) {
    int t = blockIdx.x * blockDim.x + threadIdx.x;
    if (t >= GROUPS * (HDIM / 4)) return;
    int f4 = t & (HDIM / 4 - 1);
    int g  = t >> 11;
    int s = g_gstart[g], c = g_gcount[g];
    float4 acc = make_float4(0.f, 0.f, 0.f, 0.f);
    for (int i = 0; i < c; i++) {
        float4 v = *(const float4*)&h[(size_t)(s + i) * HDIM + f4 * 4];
        acc.x += v.x; acc.y += v.y; acc.z += v.z; acc.w += v.w;
    }
    float inv = (c > 0) ? (1.f / (float)c) : 0.f;
    acc.x *= inv; acc.y *= inv; acc.z *= inv; acc.w *= inv;
    *(float4*)&g_pooled[(size_t)g * HDIM + f4 * 4] = acc;
}
__global__ void final_kernel(const float* __restrict__ lw,
                             const float* __restrict__ lb,
                             float* __restrict__ out) {
    __shared__ float red[256];
    int g = blockIdx.x;
    float s = 0.f;
    for (int f = threadIdx.x; f < HDIM; f += 256)
        s += g_pooled[(size_t)g * HDIM + f] * lw[f];
    red[threadIdx.x] = s;
    __syncthreads();
    for (int o = 128; o; o >>= 1) {
        if (threadIdx.x < o) red[threadIdx.x] += red[threadIdx.x + o];
        __syncthreads();
    }
    if (threadIdx.x == 0) out[g] = red[0] + lb[0];
}

// ---------------- launch ----------------
extern "C" void kernel_launch(void* const* d_in, const int* in_sizes, int n_in,
                              void* d_out, int out_size) {
    const float* x   = (const float*)d_in[0];
    const int*   ei  = (const int*)  d_in[1];
    const int*   bat = (const int*)  d_in[2];
    const float* W1  = (const float*)d_in[3];
    const float* as1 = (const float*)d_in[4];
    const float* ad1 = (const float*)d_in[5];
    const float* b1  = (const float*)d_in[6];
    const float* W2  = (const float*)d_in[7];
    const float* as2 = (const float*)d_in[8];
    const float* ad2 = (const float*)d_in[9];
    const float* b2  = (const float*)d_in[10];
    const float* lw  = (const float*)d_in[11];
    const float* lb  = (const float*)d_in[12];
    float* out = (float*)d_out;

    float *bufA, *bufB;
    __half *xh, *w1t, *w2t, *hh;
    cudaGetSymbolAddress((void**)&bufA, g_bufA);
    cudaGetSymbolAddress((void**)&bufB, g_bufB);
    cudaGetSymbolAddress((void**)&xh,  g_xh);
    cudaGetSymbolAddress((void**)&w1t, g_w1t);
    cudaGetSymbolAddress((void**)&w2t, g_w2t);
    cudaGetSymbolAddress((void**)&hh,  g_hh);

    const int TB = 256;
    const int edgeBlocks = (ETOT + TB - 1) / TB;

    // CSR build
    zero_meta_kernel<<<(NODES + TB - 1) / TB, TB>>>();
    deg_kernel<<<edgeBlocks, TB>>>(ei);
    scan_kernel<<<1, NODES>>>();
    fill_csr_kernel<<<edgeBlocks, TB>>>(ei);

    // fp16 conversions (weights + layer-1 input)
    f32_to_f16_pad_kernel<<<(NODES * KPAD1 / 2 + TB - 1) / TB, TB>>>(x, xh, NODES, INDIM, KPAD1);
    transpose_f16_kernel<<<dim3(HDIM / 32, KPAD1 / 32), dim3(32, 8)>>>(W1, w1t, INDIM, HDIM, KPAD1);
    transpose_f16_kernel<<<dim3(HDIM / 32, HDIM / 32), dim3(32, 8)>>>(W2, w2t, HDIM, HDIM, HDIM);

    dim3 gemmGrid(HDIM / 128, NODES / 128);   // (64, 8)
    const int aggBlocks   = NODES * (HDIM / 4) / TB;
    const int scoreBlocks = (NODES * HEADS * 32 + TB - 1) / TB;
    const int attnBlocks  = (NODES * HEADS + TB - 1) / TB;

    // ---- layer 1 ----
    gemm_hmma_kernel<<<gemmGrid, TB>>>(xh, w1t, bufA, KPAD1, HDIM);
    scores_kernel<<<scoreBlocks, TB>>>(bufA, as1, ad1);
    attn_kernel<<<attnBlocks, TB>>>();
    aggregate_kernel<__half><<<aggBlocks, TB>>>(bufA, b1, hh);   // fp16 out -> GEMM2 A

    // ---- layer 2 ----
    gemm_hmma_kernel<<<gemmGrid, TB>>>(hh, w2t, bufA, HDIM, HDIM);
    scores_kernel<<<scoreBlocks, TB>>>(bufA, as2, ad2);
    attn_kernel<<<attnBlocks, TB>>>();
    aggregate_kernel<float><<<aggBlocks, TB>>>(bufA, b2, bufB);

    // ---- pooling + classifier ----
    group_bounds_kernel<<<(NODES + TB - 1) / TB, TB>>>(bat);
    pool_kernel<<<GROUPS * (HDIM / 4) / TB, TB>>>(bufB);
    final_kernel<<<GROUPS, TB>>>(lw, lb, out);
}

// round 16
// speedup vs baseline: 1.0770x; 1.0070x over previous
#include <cuda_runtime.h>
#include <cuda_fp16.h>
#include <cstdint>

// ---------------- problem constants ----------------
static constexpr int NODES = 1024;
static constexpr int EDGES = 16384;
static constexpr int ETOT  = EDGES + NODES;   // + self loops = 17408
static constexpr int INDIM = 1300;
static constexpr int KPAD1 = 1344;            // INDIM padded to multiple of 64
static constexpr int HEADS = 16;
static constexpr int DHEAD = 512;
static constexpr int HDIM  = HEADS * DHEAD;   // 8192
static constexpr int GROUPS = 8;
static constexpr float SLOPE = 0.2f;

// ---------------- scratch (static device globals; no allocation) ----------------
__device__ __align__(16) float g_bufA[NODES * HDIM];   // GEMM output h
__device__ __align__(16) float g_bufB[NODES * HDIM];   // layer-2 aggregated output
__device__ __align__(16) __half g_xh [NODES * KPAD1];  // x in fp16, K padded
__device__ __align__(16) __half g_w1t[HDIM * KPAD1];   // W1^T fp16 [N,K]
__device__ __align__(16) __half g_w2t[HDIM * HDIM];    // W2^T fp16 [N,K]
__device__ __align__(16) __half g_hh [NODES * HDIM];   // layer-2 input fp16 (aggregate1 out)
__device__ float g_ssrc[NODES * HEADS];
__device__ float g_sdst[NODES * HEADS];
__device__ float g_alpha[ETOT * HEADS];
__device__ int   g_deg[NODES];
__device__ int   g_rp[NODES + 1];
__device__ int   g_cursor[NODES];
__device__ int   g_csr_src[ETOT];
__device__ float g_pooled[GROUPS * HDIM];
__device__ int   g_gstart[GROUPS];
__device__ int   g_gcount[GROUPS];

// ---------------- PTX helpers (arch-portable: ldmatrix / mma.sync / cp.async) ---
__device__ __forceinline__ uint32_t smem_u32(const void* p) {
    uint32_t a;
    asm("{ .reg .u64 t; cvta.to.shared.u64 t, %1; cvt.u32.u64 %0, t; }" : "=r"(a) : "l"(p));
    return a;
}
__device__ __forceinline__ void cp_async16(uint32_t dst, const void* src) {
    asm volatile("cp.async.cg.shared.global [%0], [%1], 16;" :: "r"(dst), "l"(src) : "memory");
}
__device__ __forceinline__ void ldmatrix_x4(uint32_t& r0, uint32_t& r1,
                                            uint32_t& r2, uint32_t& r3, uint32_t addr) {
    asm volatile("ldmatrix.sync.aligned.m8n8.x4.shared.b16 {%0,%1,%2,%3}, [%4];"
                 : "=r"(r0), "=r"(r1), "=r"(r2), "=r"(r3) : "r"(addr));
}
__device__ __forceinline__ void ldmatrix_x2(uint32_t& r0, uint32_t& r1, uint32_t addr) {
    asm volatile("ldmatrix.sync.aligned.m8n8.x2.shared.b16 {%0,%1}, [%2];"
                 : "=r"(r0), "=r"(r1) : "r"(addr));
}
__device__ __forceinline__ void mma16816(float* c, const uint32_t* a, const uint32_t* b) {
    asm volatile("mma.sync.aligned.m16n8k16.row.col.f32.f16.f16.f32 "
                 "{%0,%1,%2,%3}, {%4,%5,%6,%7}, {%8,%9}, {%0,%1,%2,%3};"
                 : "+f"(c[0]), "+f"(c[1]), "+f"(c[2]), "+f"(c[3])
                 : "r"(a[0]), "r"(a[1]), "r"(a[2]), "r"(a[3]), "r"(b[0]), "r"(b[1]));
}

// ---------------- fp16 conversion / transpose ----------------
__global__ void f32_to_f16_pad_kernel(const float* __restrict__ in, __half* __restrict__ out,
                                      int M, int K, int KP) {
    int i = blockIdx.x * blockDim.x + threadIdx.x;  // half2 index over M*KP/2
    if (i >= M * (KP / 2)) return;
    int m = i / (KP / 2), j = i - m * (KP / 2);
    int k = 2 * j;
    __half2 v;
    if (k + 1 < K)
        v = __floats2half2_rn(in[(size_t)m * K + k], in[(size_t)m * K + k + 1]);
    else
        v = __floats2half2_rn(0.f, 0.f);
    ((__half2*)out)[i] = v;
}

// out[n*KP + k] fp16 = in[k*N + n]; zero-pad k >= K. N % 32 == 0, KP % 32 == 0.
__global__ void transpose_f16_kernel(const float* __restrict__ in, __half* __restrict__ out,
                                     int K, int Nn, int KP) {
    __shared__ float t[32][33];
    int kBase = blockIdx.y * 32, nBase = blockIdx.x * 32;
    int tx = threadIdx.x, ty = threadIdx.y;   // (32, 8)
#pragma unroll
    for (int j = 0; j < 32; j += 8) {
        int k = kBase + ty + j;
        t[ty + j][tx] = (k < K) ? in[(size_t)k * Nn + nBase + tx] : 0.f;
    }
    __syncthreads();
#pragma unroll
    for (int j = 0; j < 32; j += 8) {
        int n = nBase + ty + j;
        out[(size_t)n * KP + kBase + tx] = __float2half_rn(t[tx][ty + j]);
    }
}

// ---------------- HMMA GEMM: C[M,N] fp32 = A[M,K]fp16 * Bt[N,K]fp16^T -----------
// 128x128 block tile, BK=32, 256 threads, 8 warps * (64x32) via m16n8k16.
// R13 pipeline structure: prefetch issued first, wait_group 1, two barriers/iter.
static constexpr int SPAD = 40;

__global__ __launch_bounds__(256) void gemm_hmma_kernel(
    const __half* __restrict__ A, const __half* __restrict__ B,
    float* __restrict__ C, int K, int Nn)
{
    __shared__ __align__(16) __half As[2][128][SPAD];
    __shared__ __align__(16) __half Bs[2][128][SPAD];

    const int tid  = threadIdx.x;
    const int lane = tid & 31, wid = tid >> 5;
    const int wm = (wid & 1) * 64;          // warp M offset in tile
    const int wn = (wid >> 1) * 32;         // warp N offset in tile
    const int rowBase = blockIdx.y * 128;
    const int colBase = blockIdx.x * 128;

    const __half* gA = A + (size_t)rowBase * K;
    const __half* gB = B + (size_t)colBase * K;

    const int ldCol = (tid & 3) * 8;        // halves within BK=32
    const int ldRow = tid >> 2;             // 0..63 (+64 for second chunk)

    float acc[4][4][4];
#pragma unroll
    for (int mi = 0; mi < 4; mi++)
#pragma unroll
        for (int ni = 0; ni < 4; ni++)
#pragma unroll
            for (int j = 0; j < 4; j++) acc[mi][ni][j] = 0.f;

    // prologue: load tile 0
#pragma unroll
    for (int i = 0; i < 2; i++) {
        int row = ldRow + i * 64;
        cp_async16(smem_u32(&As[0][row][ldCol]), gA + (size_t)row * K + ldCol);
        cp_async16(smem_u32(&Bs[0][row][ldCol]), gB + (size_t)row * K + ldCol);
    }
    asm volatile("cp.async.commit_group;" ::: "memory");

    const int T = K >> 5;
    for (int t = 0; t < T; t++) {
        const int buf = t & 1;
        if (t + 1 < T) {
            const int nbuf = buf ^ 1, k0 = (t + 1) << 5;
#pragma unroll
            for (int i = 0; i < 2; i++) {
                int row = ldRow + i * 64;
                cp_async16(smem_u32(&As[nbuf][row][ldCol]), gA + (size_t)row * K + k0 + ldCol);
                cp_async16(smem_u32(&Bs[nbuf][row][ldCol]), gB + (size_t)row * K + k0 + ldCol);
            }
            asm volatile("cp.async.commit_group;" ::: "memory");
            asm volatile("cp.async.wait_group 1;" ::: "memory");
        } else {
            asm volatile("cp.async.wait_group 0;" ::: "memory");
        }
        __syncthreads();   // tile t resident

#pragma unroll
        for (int kk = 0; kk < 32; kk += 16) {
            uint32_t af[4][4], bf[4][2];
#pragma unroll
            for (int mi = 0; mi < 4; mi++) {
                uint32_t addr = smem_u32(
                    &As[buf][wm + mi * 16 + (lane & 15)][kk + (lane >> 4) * 8]);
                ldmatrix_x4(af[mi][0], af[mi][1], af[mi][2], af[mi][3], addr);
            }
#pragma unroll
            for (int ni = 0; ni < 4; ni++) {
                int l16 = lane & 15;
                uint32_t addr = smem_u32(
                    &Bs[buf][wn + ni * 8 + (l16 & 7)][kk + (l16 >> 3) * 8]);
                ldmatrix_x2(bf[ni][0], bf[ni][1], addr);
            }
#pragma unroll
            for (int mi = 0; mi < 4; mi++)
#pragma unroll
                for (int ni = 0; ni < 4; ni++)
                    mma16816(acc[mi][ni], af[mi], bf[ni]);
        }
        __syncthreads();   // compute done before buf is overwritten at t+2
    }

    // epilogue: c0,c1 at (row = lane>>2, col = 2*(lane&3)), c2,c3 at row+8
#pragma unroll
    for (int mi = 0; mi < 4; mi++) {
        int r0 = rowBase + wm + mi * 16 + (lane >> 2);
#pragma unroll
        for (int ni = 0; ni < 4; ni++) {
            int c0 = colBase + wn + ni * 8 + (lane & 3) * 2;
            *(float2*)&C[(size_t)r0 * Nn + c0]       = make_float2(acc[mi][ni][0], acc[mi][ni][1]);
            *(float2*)&C[(size_t)(r0 + 8) * Nn + c0] = make_float2(acc[mi][ni][2], acc[mi][ni][3]);
        }
    }
}

// ---------------- CSR build (dst-grouped) ----------------
__global__ void zero_meta_kernel() {
    int i = blockIdx.x * blockDim.x + threadIdx.x;
    if (i < NODES) g_deg[i] = 0;
    if (i < GROUPS) { g_gcount[i] = 0; g_gstart[i] = 0; }
}
__global__ void deg_kernel(const int* __restrict__ ei) {
    int k = blockIdx.x * blockDim.x + threadIdx.x;
    if (k >= ETOT) return;
    int dst = (k < EDGES) ? ei[EDGES + k] : (k - EDGES);
    atomicAdd(&g_deg[dst], 1);
}
__global__ void scan_kernel() {
    __shared__ int s[NODES];
    int t = threadIdx.x;
    int d = g_deg[t];
    s[t] = d;
    __syncthreads();
    for (int o = 1; o < NODES; o <<= 1) {
        int v = (t >= o) ? s[t - o] : 0;
        __syncthreads();
        s[t] += v;
        __syncthreads();
    }
    if (t == 0) g_rp[0] = 0;
    g_rp[t + 1] = s[t];
    g_cursor[t] = s[t] - d;
}
__global__ void fill_csr_kernel(const int* __restrict__ ei) {
    int k = blockIdx.x * blockDim.x + threadIdx.x;
    if (k >= ETOT) return;
    int src, dst;
    if (k < EDGES) { src = ei[k]; dst = ei[EDGES + k]; }
    else           { src = dst = k - EDGES; }
    int pos = atomicAdd(&g_cursor[dst], 1);
    g_csr_src[pos] = src;
}

// ---------------- attention ----------------
__global__ void scores_kernel(const float* __restrict__ h,
                              const float* __restrict__ a_src,
                              const float* __restrict__ a_dst) {
    int warpId = (blockIdx.x * blockDim.x + threadIdx.x) >> 5;
    int lane = threadIdx.x & 31;
    if (warpId >= NODES * HEADS) return;
    int n = warpId / HEADS, hh = warpId % HEADS;
    const float* hp  = h + (size_t)n * HDIM + hh * DHEAD;
    const float* asp = a_src + hh * DHEAD;
    const float* adp = a_dst + hh * DHEAD;
    float ss = 0.f, sd = 0.f;
    for (int d = lane; d < DHEAD; d += 32) {
        float v = hp[d];
        ss += v * asp[d];
        sd += v * adp[d];
    }
#pragma unroll
    for (int o = 16; o; o >>= 1) {
        ss += __shfl_xor_sync(0xffffffffu, ss, o);
        sd += __shfl_xor_sync(0xffffffffu, sd, o);
    }
    if (lane == 0) {
        g_ssrc[n * HEADS + hh] = ss;
        g_sdst[n * HEADS + hh] = sd;
    }
}

__global__ void attn_kernel() {
    int t = blockIdx.x * blockDim.x + threadIdx.x;
    if (t >= NODES * HEADS) return;
    int hh = t % HEADS, n = t / HEADS;
    float sd = g_sdst[n * HEADS + hh];
    int b = g_rp[n], e = g_rp[n + 1];
    float m = -1e30f;
    for (int i = b; i < e; i++) {
        float x = g_ssrc[g_csr_src[i] * HEADS + hh] + sd;
        x = (x > 0.f) ? x : SLOPE * x;
        m = fmaxf(m, x);
    }
    float sum = 0.f;
    for (int i = b; i < e; i++) {
        float x = g_ssrc[g_csr_src[i] * HEADS + hh] + sd;
        x = (x > 0.f) ? x : SLOPE * x;
        float p = __expf(x - m);
        sum += p;
        g_alpha[i * HEADS + hh] = p;
    }
    float inv = 1.f / sum;
    for (int i = b; i < e; i++) g_alpha[i * HEADS + hh] *= inv;
}

// out[n,f] = relu( sum_{edges into n} alpha * h[src,f] + bias[f] )
// 4x unrolled edge loop (4 independent gather chains -> MLP 4 on L2 hits).
// OutT = __half (layer 1, feeds GEMM2 A) or float (layer 2, feeds pooling).
template <typename OutT>
__global__ void aggregate_kernel(const float* __restrict__ h,
                                 const float* __restrict__ bias,
                                 OutT* __restrict__ out) {
    int t = blockIdx.x * blockDim.x + threadIdx.x;
    if (t >= NODES * (HDIM / 4)) return;
    int f4 = t & (HDIM / 4 - 1);
    int n  = t >> 11;
    int hh = f4 >> 7;
    int b = g_rp[n], e = g_rp[n + 1];
    float4 acc = make_float4(0.f, 0.f, 0.f, 0.f);

    int i = b;
    for (; i + 4 <= e; i += 4) {
        int s0 = g_csr_src[i],     s1 = g_csr_src[i + 1];
        int s2 = g_csr_src[i + 2], s3 = g_csr_src[i + 3];
        float a0 = __ldg(&g_alpha[(i    ) * HEADS + hh]);
        float a1 = __ldg(&g_alpha[(i + 1) * HEADS + hh]);
        float a2 = __ldg(&g_alpha[(i + 2) * HEADS + hh]);
        float a3 = __ldg(&g_alpha[(i + 3) * HEADS + hh]);
        float4 v0 = *(const float4*)&h[(size_t)s0 * HDIM + f4 * 4];
        float4 v1 = *(const float4*)&h[(size_t)s1 * HDIM + f4 * 4];
        float4 v2 = *(const float4*)&h[(size_t)s2 * HDIM + f4 * 4];
        float4 v3 = *(const float4*)&h[(size_t)s3 * HDIM + f4 * 4];
        acc.x += a0 * v0.x + a1 * v1.x + a2 * v2.x + a3 * v3.x;
        acc.y += a0 * v0.y + a1 * v1.y + a2 * v2.y + a3 * v3.y;
        acc.z += a0 * v0.z + a1 * v1.z + a2 * v2.z + a3 * v3.z;
        acc.w += a0 * v0.w + a1 * v1.w + a2 * v2.w + a3 * v3.w;
    }
    for (; i < e; i++) {
        float a = __ldg(&g_alpha[i * HEADS + hh]);
        float4 v = *(const float4*)&h[(size_t)g_csr_src[i] * HDIM + f4 * 4];
        acc.x += a * v.x; acc.y += a * v.y; acc.z += a * v.z; acc.w += a * v.w;
    }

    float4 bb = *(const float4*)&bias[f4 * 4];
    acc.x = fmaxf(acc.x + bb.x, 0.f);
    acc.y = fmaxf(acc.y + bb.y, 0.f);
    acc.z = fmaxf(acc.z + bb.z, 0.f);
    acc.w = fmaxf(acc.w + bb.w, 0.f);

    if constexpr (sizeof(OutT) == 2) {
        __half2 lo = __floats2half2_rn(acc.x, acc.y);
        __half2 hi = __floats2half2_rn(acc.z, acc.w);
        __half2* op = (__half2*)&out[(size_t)n * HDIM + f4 * 4];
        op[0] = lo; op[1] = hi;
    } else {
        *(float4*)&out[(size_t)n * HDIM + f4 * 4] = acc;
    }
}

// ---------------- pooling + classifier ----------------
__global__ void group_bounds_kernel(const int* __restrict__ batch) {
    int n = blockIdx.x * blockDim.x + threadIdx.x;
    if (n >= NODES) return;
    int g = batch[n];
    atomicAdd(&g_gcount[g], 1);
    if (n == 0 || batch[n - 1] != g) g_gstart[g] = n;
}
__global__ void pool_kernel(const float* __restrict__ h) {
    int t = blockIdx.x * blockDim.x + threadIdx.x;
    if (t >= GROUPS * (HDIM / 4)) return;
    int f4 = t & (HDIM / 4 - 1);
    int g  = t >> 11;
    int s = g_gstart[g], c = g_gcount[g];
    float4 acc = make_float4(0.f, 0.f, 0.f, 0.f);
    for (int i = 0; i < c; i++) {
        float4 v = *(const float4*)&h[(size_t)(s + i) * HDIM + f4 * 4];
        acc.x += v.x; acc.y += v.y; acc.z += v.z; acc.w += v.w;
    }
    float inv = (c > 0) ? (1.f / (float)c) : 0.f;
    acc.x *= inv; acc.y *= inv; acc.z *= inv; acc.w *= inv;
    *(float4*)&g_pooled[(size_t)g * HDIM + f4 * 4] = acc;
}
__global__ void final_kernel(const float* __restrict__ lw,
                             const float* __restrict__ lb,
                             float* __restrict__ out) {
    __shared__ float red[256];
    int g = blockIdx.x;
    float s = 0.f;
    for (int f = threadIdx.x; f < HDIM; f += 256)
        s += g_pooled[(size_t)g * HDIM + f] * lw[f];
    red[threadIdx.x] = s;
    __syncthreads();
    for (int o = 128; o; o >>= 1) {
        if (threadIdx.x < o) red[threadIdx.x] += red[threadIdx.x + o];
        __syncthreads();
    }
    if (threadIdx.x == 0) out[g] = red[0] + lb[0];
}

// ---------------- launch ----------------
extern "C" void kernel_launch(void* const* d_in, const int* in_sizes, int n_in,
                              void* d_out, int out_size) {
    const float* x   = (const float*)d_in[0];
    const int*   ei  = (const int*)  d_in[1];
    const int*   bat = (const int*)  d_in[2];
    const float* W1  = (const float*)d_in[3];
    const float* as1 = (const float*)d_in[4];
    const float* ad1 = (const float*)d_in[5];
    const float* b1  = (const float*)d_in[6];
    const float* W2  = (const float*)d_in[7];
    const float* as2 = (const float*)d_in[8];
    const float* ad2 = (const float*)d_in[9];
    const float* b2  = (const float*)d_in[10];
    const float* lw  = (const float*)d_in[11];
    const float* lb  = (const float*)d_in[12];
    float* out = (float*)d_out;

    float *bufA, *bufB;
    __half *xh, *w1t, *w2t, *hh;
    cudaGetSymbolAddress((void**)&bufA, g_bufA);
    cudaGetSymbolAddress((void**)&bufB, g_bufB);
    cudaGetSymbolAddress((void**)&xh,  g_xh);
    cudaGetSymbolAddress((void**)&w1t, g_w1t);
    cudaGetSymbolAddress((void**)&w2t, g_w2t);
    cudaGetSymbolAddress((void**)&hh,  g_hh);

    const int TB = 256;
    const int edgeBlocks = (ETOT + TB - 1) / TB;

    // CSR build
    zero_meta_kernel<<<(NODES + TB - 1) / TB, TB>>>();
    deg_kernel<<<edgeBlocks, TB>>>(ei);
    scan_kernel<<<1, NODES>>>();
    fill_csr_kernel<<<edgeBlocks, TB>>>(ei);

    // fp16 conversions (weights + layer-1 input)
    f32_to_f16_pad_kernel<<<(NODES * KPAD1 / 2 + TB - 1) / TB, TB>>>(x, xh, NODES, INDIM, KPAD1);
    transpose_f16_kernel<<<dim3(HDIM / 32, KPAD1 / 32), dim3(32, 8)>>>(W1, w1t, INDIM, HDIM, KPAD1);
    transpose_f16_kernel<<<dim3(HDIM / 32, HDIM / 32), dim3(32, 8)>>>(W2, w2t, HDIM, HDIM, HDIM);

    dim3 gemmGrid(HDIM / 128, NODES / 128);   // (64, 8)
    const int aggBlocks   = NODES * (HDIM / 4) / TB;
    const int scoreBlocks = (NODES * HEADS * 32 + TB - 1) / TB;
    const int attnBlocks  = (NODES * HEADS + TB - 1) / TB;

    // ---- layer 1 ----
    gemm_hmma_kernel<<<gemmGrid, TB>>>(xh, w1t, bufA, KPAD1, HDIM);
    scores_kernel<<<scoreBlocks, TB>>>(bufA, as1, ad1);
    attn_kernel<<<attnBlocks, TB>>>();
    aggregate_kernel<__half><<<aggBlocks, TB>>>(bufA, b1, hh);   // fp16 out -> GEMM2 A

    // ---- layer 2 ----
    gemm_hmma_kernel<<<gemmGrid, TB>>>(hh, w2t, bufA, HDIM, HDIM);
    scores_kernel<<<scoreBlocks, TB>>>(bufA, as2, ad2);
    attn_kernel<<<attnBlocks, TB>>>();
    aggregate_kernel<float><<<aggBlocks, TB>>>(bufA, b2, bufB);

    // ---- pooling + classifier ----
    group_bounds_kernel<<<(NODES + TB - 1) / TB, TB>>>(bat);
    pool_kernel<<<GROUPS * (HDIM / 4) / TB, TB>>>(bufB);
    final_kernel<<<GROUPS, TB>>>(lw, lb, out);
}

// round 17
// speedup vs baseline: 1.1674x; 1.0839x over previous
#include <cuda_runtime.h>
#include <cuda_fp16.h>
#include <cstdint>

// ---------------- problem constants ----------------
static constexpr int NODES = 1024;
static constexpr int EDGES = 16384;
static constexpr int ETOT  = EDGES + NODES;   // + self loops = 17408
static constexpr int INDIM = 1300;
static constexpr int KPAD1 = 1344;            // INDIM padded to multiple of 64
static constexpr int HEADS = 16;
static constexpr int DHEAD = 512;
static constexpr int HDIM  = HEADS * DHEAD;   // 8192
static constexpr int GROUPS = 8;
static constexpr float SLOPE = 0.2f;

// ---------------- scratch (static device globals; no allocation) ----------------
__device__ __align__(16) float g_bufA[NODES * HDIM];   // GEMM output h
__device__ __align__(16) float g_bufB[NODES * HDIM];   // layer-2 aggregated output
__device__ __align__(16) __half g_xh [NODES * KPAD1];  // x in fp16, K padded
__device__ __align__(16) __half g_w1t[HDIM * KPAD1];   // W1^T fp16 [N,K]
__device__ __align__(16) __half g_w2t[HDIM * HDIM];    // W2^T fp16 [N,K]
__device__ __align__(16) __half g_hh [NODES * HDIM];   // layer-2 input fp16 (aggregate1 out)
__device__ float g_ssrc[NODES * HEADS];
__device__ float g_sdst[NODES * HEADS];
__device__ float g_alpha[ETOT * HEADS];
__device__ int   g_deg[NODES];
__device__ int   g_rp[NODES + 1];
__device__ int   g_cursor[NODES];
__device__ int   g_csr_src[ETOT];
__device__ float g_pooled[GROUPS * HDIM];
__device__ int   g_gstart[GROUPS];
__device__ int   g_gcount[GROUPS];

// ---------------- PTX helpers (arch-portable: ldmatrix / mma.sync / cp.async) ---
__device__ __forceinline__ uint32_t smem_u32(const void* p) {
    uint32_t a;
    asm("{ .reg .u64 t; cvta.to.shared.u64 t, %1; cvt.u32.u64 %0, t; }" : "=r"(a) : "l"(p));
    return a;
}
__device__ __forceinline__ void cp_async16(uint32_t dst, const void* src) {
    asm volatile("cp.async.cg.shared.global [%0], [%1], 16;" :: "r"(dst), "l"(src) : "memory");
}
__device__ __forceinline__ void ldmatrix_x4(uint32_t& r0, uint32_t& r1,
                                            uint32_t& r2, uint32_t& r3, uint32_t addr) {
    asm volatile("ldmatrix.sync.aligned.m8n8.x4.shared.b16 {%0,%1,%2,%3}, [%4];"
                 : "=r"(r0), "=r"(r1), "=r"(r2), "=r"(r3) : "r"(addr));
}
__device__ __forceinline__ void ldmatrix_x2(uint32_t& r0, uint32_t& r1, uint32_t addr) {
    asm volatile("ldmatrix.sync.aligned.m8n8.x2.shared.b16 {%0,%1}, [%2];"
                 : "=r"(r0), "=r"(r1) : "r"(addr));
}
__device__ __forceinline__ void mma16816(float* c, const uint32_t* a, const uint32_t* b) {
    asm volatile("mma.sync.aligned.m16n8k16.row.col.f32.f16.f16.f32 "
                 "{%0,%1,%2,%3}, {%4,%5,%6,%7}, {%8,%9}, {%0,%1,%2,%3};"
                 : "+f"(c[0]), "+f"(c[1]), "+f"(c[2]), "+f"(c[3])
                 : "r"(a[0]), "r"(a[1]), "r"(a[2]), "r"(a[3]), "r"(b[0]), "r"(b[1]));
}

// ---------------- fp16 conversion / transpose ----------------
__global__ void f32_to_f16_pad_kernel(const float* __restrict__ in, __half* __restrict__ out,
                                      int M, int K, int KP) {
    int i = blockIdx.x * blockDim.x + threadIdx.x;  // half2 index over M*KP/2
    if (i >= M * (KP / 2)) return;
    int m = i / (KP / 2), j = i - m * (KP / 2);
    int k = 2 * j;
    __half2 v;
    if (k + 1 < K)
        v = __floats2half2_rn(in[(size_t)m * K + k], in[(size_t)m * K + k + 1]);
    else
        v = __floats2half2_rn(0.f, 0.f);
    ((__half2*)out)[i] = v;
}

// out[n*KP + k] fp16 = in[k*N + n]; zero-pad k >= K. N % 32 == 0, KP % 32 == 0.
__global__ void transpose_f16_kernel(const float* __restrict__ in, __half* __restrict__ out,
                                     int K, int Nn, int KP) {
    __shared__ float t[32][33];
    int kBase = blockIdx.y * 32, nBase = blockIdx.x * 32;
    int tx = threadIdx.x, ty = threadIdx.y;   // (32, 8)
#pragma unroll
    for (int j = 0; j < 32; j += 8) {
        int k = kBase + ty + j;
        t[ty + j][tx] = (k < K) ? in[(size_t)k * Nn + nBase + tx] : 0.f;
    }
    __syncthreads();
#pragma unroll
    for (int j = 0; j < 32; j += 8) {
        int n = nBase + ty + j;
        out[(size_t)n * KP + kBase + tx] = __float2half_rn(t[tx][ty + j]);
    }
}

// ---------------- HMMA GEMM: C[M,N] fp32 = A[M,K]fp16 * Bt[N,K]fp16^T -----------
// 128x128 block tile, BK=32, 128 threads (4 warps), warp tile 64x64 via m16n8k16.
// 3-stage cp.async pipeline: one __syncthreads + wait_group 1 per K-iter.
static constexpr int SPAD = 40;                      // halves per smem row (80 B)
static constexpr int STAGE_BYTES = 2 * 128 * SPAD * 2;   // As+Bs per stage = 20480
static constexpr int GEMM_SMEM = 3 * STAGE_BYTES;        // 61440

__global__ __launch_bounds__(128) void gemm_hmma_kernel(
    const __half* __restrict__ A, const __half* __restrict__ B,
    float* __restrict__ C, int K, int Nn)
{
    extern __shared__ __align__(16) char smem[];
    // stage s: A rows at smem + s*STAGE_BYTES, B rows at +128*SPAD*2
    auto As = [&](int s, int r) -> __half* {
        return (__half*)(smem + s * STAGE_BYTES) + r * SPAD;
    };
    auto Bs = [&](int s, int r) -> __half* {
        return (__half*)(smem + s * STAGE_BYTES + 128 * SPAD * 2) + r * SPAD;
    };

    const int tid  = threadIdx.x;
    const int lane = tid & 31, wid = tid >> 5;
    const int wm = (wid & 1) * 64;          // warp M offset in tile
    const int wn = (wid >> 1) * 64;         // warp N offset in tile
    const int rowBase = blockIdx.y * 128;
    const int colBase = blockIdx.x * 128;

    const __half* gA = A + (size_t)rowBase * K;
    const __half* gB = B + (size_t)colBase * K;

    const int ldRow = tid >> 2;             // 0..31 (+32*i)
    const int ldCol = (tid & 3) * 8;        // halves within BK=32

    // issue the 8 cp.async16 for stage s, K-offset k0
    auto load_stage = [&](int s, int k0) {
#pragma unroll
        for (int i = 0; i < 4; i++) {
            int row = ldRow + i * 32;
            cp_async16(smem_u32(As(s, row) + ldCol), gA + (size_t)row * K + k0 + ldCol);
            cp_async16(smem_u32(Bs(s, row) + ldCol), gB + (size_t)row * K + k0 + ldCol);
        }
    };

    float acc[4][8][4];
#pragma unroll
    for (int mi = 0; mi < 4; mi++)
#pragma unroll
        for (int ni = 0; ni < 8; ni++)
#pragma unroll
            for (int j = 0; j < 4; j++) acc[mi][ni][j] = 0.f;

    const int T = K >> 5;
    // prologue: stages 0 and 1
    load_stage(0, 0);
    asm volatile("cp.async.commit_group;" ::: "memory");
    load_stage(1, 32);
    asm volatile("cp.async.commit_group;" ::: "memory");

    for (int t = 0; t < T; t++) {
        const int s = t % 3;
        asm volatile("cp.async.wait_group 1;" ::: "memory");   // stage t complete
        __syncthreads();                                        // visible to all; all warps done with t-1
        if (t + 2 < T) load_stage((t + 2) % 3, (t + 2) << 5);   // slot (t-1)%3, proven free
        asm volatile("cp.async.commit_group;" ::: "memory");    // commit (possibly empty) group

#pragma unroll
        for (int kk = 0; kk < 32; kk += 16) {
            uint32_t af[4][4], bf[8][2];
#pragma unroll
            for (int mi = 0; mi < 4; mi++) {
                uint32_t addr = smem_u32(
                    As(s, wm + mi * 16 + (lane & 15)) + kk + (lane >> 4) * 8);
                ldmatrix_x4(af[mi][0], af[mi][1], af[mi][2], af[mi][3], addr);
            }
            int l16 = lane & 15;
#pragma unroll
            for (int ni = 0; ni < 8; ni++) {
                uint32_t addr = smem_u32(
                    Bs(s, wn + ni * 8 + (l16 & 7)) + kk + (l16 >> 3) * 8);
                ldmatrix_x2(bf[ni][0], bf[ni][1], addr);
            }
#pragma unroll
            for (int mi = 0; mi < 4; mi++)
#pragma unroll
                for (int ni = 0; ni < 8; ni++)
                    mma16816(acc[mi][ni], af[mi], bf[ni]);
        }
    }

    // epilogue: c0,c1 at (row = lane>>2, col = 2*(lane&3)), c2,c3 at row+8
#pragma unroll
    for (int mi = 0; mi < 4; mi++) {
        int r0 = rowBase + wm + mi * 16 + (lane >> 2);
#pragma unroll
        for (int ni = 0; ni < 8; ni++) {
            int c0 = colBase + wn + ni * 8 + (lane & 3) * 2;
            *(float2*)&C[(size_t)r0 * Nn + c0]       = make_float2(acc[mi][ni][0], acc[mi][ni][1]);
            *(float2*)&C[(size_t)(r0 + 8) * Nn + c0] = make_float2(acc[mi][ni][2], acc[mi][ni][3]);
        }
    }
}

// ---------------- CSR build (dst-grouped) ----------------
__global__ void zero_meta_kernel() {
    int i = blockIdx.x * blockDim.x + threadIdx.x;
    if (i < NODES) g_deg[i] = 0;
    if (i < GROUPS) { g_gcount[i] = 0; g_gstart[i] = 0; }
}
__global__ void deg_kernel(const int* __restrict__ ei) {
    int k = blockIdx.x * blockDim.x + threadIdx.x;
    if (k >= ETOT) return;
    int dst = (k < EDGES) ? ei[EDGES + k] : (k - EDGES);
    atomicAdd(&g_deg[dst], 1);
}
__global__ void scan_kernel() {
    __shared__ int s[NODES];
    int t = threadIdx.x;
    int d = g_deg[t];
    s[t] = d;
    __syncthreads();
    for (int o = 1; o < NODES; o <<= 1) {
        int v = (t >= o) ? s[t - o] : 0;
        __syncthreads();
        s[t] += v;
        __syncthreads();
    }
    if (t == 0) g_rp[0] = 0;
    g_rp[t + 1] = s[t];
    g_cursor[t] = s[t] - d;
}
__global__ void fill_csr_kernel(const int* __restrict__ ei) {
    int k = blockIdx.x * blockDim.x + threadIdx.x;
    if (k >= ETOT) return;
    int src, dst;
    if (k < EDGES) { src = ei[k]; dst = ei[EDGES + k]; }
    else           { src = dst = k - EDGES; }
    int pos = atomicAdd(&g_cursor[dst], 1);
    g_csr_src[pos] = src;
}

// ---------------- attention ----------------
__global__ void scores_kernel(const float* __restrict__ h,
                              const float* __restrict__ a_src,
                              const float* __restrict__ a_dst) {
    int warpId = (blockIdx.x * blockDim.x + threadIdx.x) >> 5;
    int lane = threadIdx.x & 31;
    if (warpId >= NODES * HEADS) return;
    int n = warpId / HEADS, hh = warpId % HEADS;
    const float* hp  = h + (size_t)n * HDIM + hh * DHEAD;
    const float* asp = a_src + hh * DHEAD;
    const float* adp = a_dst + hh * DHEAD;
    float ss = 0.f, sd = 0.f;
    for (int d = lane; d < DHEAD; d += 32) {
        float v = hp[d];
        ss += v * asp[d];
        sd += v * adp[d];
    }
#pragma unroll
    for (int o = 16; o; o >>= 1) {
        ss += __shfl_xor_sync(0xffffffffu, ss, o);
        sd += __shfl_xor_sync(0xffffffffu, sd, o);
    }
    if (lane == 0) {
        g_ssrc[n * HEADS + hh] = ss;
        g_sdst[n * HEADS + hh] = sd;
    }
}

__global__ void attn_kernel() {
    int t = blockIdx.x * blockDim.x + threadIdx.x;
    if (t >= NODES * HEADS) return;
    int hh = t % HEADS, n = t / HEADS;
    float sd = g_sdst[n * HEADS + hh];
    int b = g_rp[n], e = g_rp[n + 1];
    float m = -1e30f;
    for (int i = b; i < e; i++) {
        float x = g_ssrc[g_csr_src[i] * HEADS + hh] + sd;
        x = (x > 0.f) ? x : SLOPE * x;
        m = fmaxf(m, x);
    }
    float sum = 0.f;
    for (int i = b; i < e; i++) {
        float x = g_ssrc[g_csr_src[i] * HEADS + hh] + sd;
        x = (x > 0.f) ? x : SLOPE * x;
        float p = __expf(x - m);
        sum += p;
        g_alpha[i * HEADS + hh] = p;
    }
    float inv = 1.f / sum;
    for (int i = b; i < e; i++) g_alpha[i * HEADS + hh] *= inv;
}

// out[n,f] = relu( sum_{edges into n} alpha * h[src,f] + bias[f] )
// 4x unrolled edge loop (4 independent gather chains -> MLP 4 on L2 hits).
// OutT = __half (layer 1, feeds GEMM2 A) or float (layer 2, feeds pooling).
template <typename OutT>
__global__ void aggregate_kernel(const float* __restrict__ h,
                                 const float* __restrict__ bias,
                                 OutT* __restrict__ out) {
    int t = blockIdx.x * blockDim.x + threadIdx.x;
    if (t >= NODES * (HDIM / 4)) return;
    int f4 = t & (HDIM / 4 - 1);
    int n  = t >> 11;
    int hh = f4 >> 7;
    int b = g_rp[n], e = g_rp[n + 1];
    float4 acc = make_float4(0.f, 0.f, 0.f, 0.f);

    int i = b;
    for (; i + 4 <= e; i += 4) {
        int s0 = g_csr_src[i],     s1 = g_csr_src[i + 1];
        int s2 = g_csr_src[i + 2], s3 = g_csr_src[i + 3];
        float a0 = __ldg(&g_alpha[(i    ) * HEADS + hh]);
        float a1 = __ldg(&g_alpha[(i + 1) * HEADS + hh]);
        float a2 = __ldg(&g_alpha[(i + 2) * HEADS + hh]);
        float a3 = __ldg(&g_alpha[(i + 3) * HEADS + hh]);
        float4 v0 = *(const float4*)&h[(size_t)s0 * HDIM + f4 * 4];
        float4 v1 = *(const float4*)&h[(size_t)s1 * HDIM + f4 * 4];
        float4 v2 = *(const float4*)&h[(size_t)s2 * HDIM + f4 * 4];
        float4 v3 = *(const float4*)&h[(size_t)s3 * HDIM + f4 * 4];
        acc.x += a0 * v0.x + a1 * v1.x + a2 * v2.x + a3 * v3.x;
        acc.y += a0 * v0.y + a1 * v1.y + a2 * v2.y + a3 * v3.y;
        acc.z += a0 * v0.z + a1 * v1.z + a2 * v2.z + a3 * v3.z;
        acc.w += a0 * v0.w + a1 * v1.w + a2 * v2.w + a3 * v3.w;
    }
    for (; i < e; i++) {
        float a = __ldg(&g_alpha[i * HEADS + hh]);
        float4 v = *(const float4*)&h[(size_t)g_csr_src[i] * HDIM + f4 * 4];
        acc.x += a * v.x; acc.y += a * v.y; acc.z += a * v.z; acc.w += a * v.w;
    }

    float4 bb = *(const float4*)&bias[f4 * 4];
    acc.x = fmaxf(acc.x + bb.x, 0.f);
    acc.y = fmaxf(acc.y + bb.y, 0.f);
    acc.z = fmaxf(acc.z + bb.z, 0.f);
    acc.w = fmaxf(acc.w + bb.w, 0.f);

    if constexpr (sizeof(OutT) == 2) {
        __half2 lo = __floats2half2_rn(acc.x, acc.y);
        __half2 hi = __floats2half2_rn(acc.z, acc.w);
        __half2* op = (__half2*)&out[(size_t)n * HDIM + f4 * 4];
        op[0] = lo; op[1] = hi;
    } else {
        *(float4*)&out[(size_t)n * HDIM + f4 * 4] = acc;
    }
}

// ---------------- pooling + classifier ----------------
__global__ void group_bounds_kernel(const int* __restrict__ batch) {
    int n = blockIdx.x * blockDim.x + threadIdx.x;
    if (n >= NODES) return;
    int g = batch[n];
    atomicAdd(&g_gcount[g], 1);
    if (n == 0 || batch[n - 1] != g) g_gstart[g] = n;
}
__global__ void pool_kernel(const float* __restrict__ h) {
    int t = blockIdx.x * blockDim.x + threadIdx.x;
    if (t >= GROUPS * (HDIM / 4)) return;
    int f4 = t & (HDIM / 4 - 1);
    int g  = t >> 11;
    int s = g_gstart[g], c = g_gcount[g];
    float4 acc = make_float4(0.f, 0.f, 0.f, 0.f);
    for (int i = 0; i < c; i++) {
        float4 v = *(const float4*)&h[(size_t)(s + i) * HDIM + f4 * 4];
        acc.x += v.x; acc.y += v.y; acc.z += v.z; acc.w += v.w;
    }
    float inv = (c > 0) ? (1.f / (float)c) : 0.f;
    acc.x *= inv; acc.y *= inv; acc.z *= inv; acc.w *= inv;
    *(float4*)&g_pooled[(size_t)g * HDIM + f4 * 4] = acc;
}
__global__ void final_kernel(const float* __restrict__ lw,
                             const float* __restrict__ lb,
                             float* __restrict__ out) {
    __shared__ float red[256];
    int g = blockIdx.x;
    float s = 0.f;
    for (int f = threadIdx.x; f < HDIM; f += 256)
        s += g_pooled[(size_t)g * HDIM + f] * lw[f];
    red[threadIdx.x] = s;
    __syncthreads();
    for (int o = 128; o; o >>= 1) {
        if (threadIdx.x < o) red[threadIdx.x] += red[threadIdx.x + o];
        __syncthreads();
    }
    if (threadIdx.x == 0) out[g] = red[0] + lb[0];
}

// ---------------- launch ----------------
extern "C" void kernel_launch(void* const* d_in, const int* in_sizes, int n_in,
                              void* d_out, int out_size) {
    const float* x   = (const float*)d_in[0];
    const int*   ei  = (const int*)  d_in[1];
    const int*   bat = (const int*)  d_in[2];
    const float* W1  = (const float*)d_in[3];
    const float* as1 = (const float*)d_in[4];
    const float* ad1 = (const float*)d_in[5];
    const float* b1  = (const float*)d_in[6];
    const float* W2  = (const float*)d_in[7];
    const float* as2 = (const float*)d_in[8];
    const float* ad2 = (const float*)d_in[9];
    const float* b2  = (const float*)d_in[10];
    const float* lw  = (const float*)d_in[11];
    const float* lb  = (const float*)d_in[12];
    float* out = (float*)d_out;

    float *bufA, *bufB;
    __half *xh, *w1t, *w2t, *hh;
    cudaGetSymbolAddress((void**)&bufA, g_bufA);
    cudaGetSymbolAddress((void**)&bufB, g_bufB);
    cudaGetSymbolAddress((void**)&xh,  g_xh);
    cudaGetSymbolAddress((void**)&w1t, g_w1t);
    cudaGetSymbolAddress((void**)&w2t, g_w2t);
    cudaGetSymbolAddress((void**)&hh,  g_hh);

    cudaFuncSetAttribute(gemm_hmma_kernel,
                         cudaFuncAttributeMaxDynamicSharedMemorySize, GEMM_SMEM);

    const int TB = 256;
    const int edgeBlocks = (ETOT + TB - 1) / TB;

    // CSR build
    zero_meta_kernel<<<(NODES + TB - 1) / TB, TB>>>();
    deg_kernel<<<edgeBlocks, TB>>>(ei);
    scan_kernel<<<1, NODES>>>();
    fill_csr_kernel<<<edgeBlocks, TB>>>(ei);

    // fp16 conversions (weights + layer-1 input)
    f32_to_f16_pad_kernel<<<(NODES * KPAD1 / 2 + TB - 1) / TB, TB>>>(x, xh, NODES, INDIM, KPAD1);
    transpose_f16_kernel<<<dim3(HDIM / 32, KPAD1 / 32), dim3(32, 8)>>>(W1, w1t, INDIM, HDIM, KPAD1);
    transpose_f16_kernel<<<dim3(HDIM / 32, HDIM / 32), dim3(32, 8)>>>(W2, w2t, HDIM, HDIM, HDIM);

    dim3 gemmGrid(HDIM / 128, NODES / 128);   // (64, 8)
    const int aggBlocks   = NODES * (HDIM / 4) / TB;
    const int scoreBlocks = (NODES * HEADS * 32 + TB - 1) / TB;
    const int attnBlocks  = (NODES * HEADS + TB - 1) / TB;

    // ---- layer 1 ----
    gemm_hmma_kernel<<<gemmGrid, 128, GEMM_SMEM>>>(xh, w1t, bufA, KPAD1, HDIM);
    scores_kernel<<<scoreBlocks, TB>>>(bufA, as1, ad1);
    attn_kernel<<<attnBlocks, TB>>>();
    aggregate_kernel<__half><<<aggBlocks, TB>>>(bufA, b1, hh);   // fp16 out -> GEMM2 A

    // ---- layer 2 ----
    gemm_hmma_kernel<<<gemmGrid, 128, GEMM_SMEM>>>(hh, w2t, bufA, HDIM, HDIM);
    scores_kernel<<<scoreBlocks, TB>>>(bufA, as2, ad2);
    attn_kernel<<<attnBlocks, TB>>>();
    aggregate_kernel<float><<<aggBlocks, TB>>>(bufA, b2, bufB);

    // ---- pooling + classifier ----
    group_bounds_kernel<<<(NODES + TB - 1) / TB, TB>>>(bat);
    pool_kernel<<<GROUPS * (HDIM / 4) / TB, TB>>>(bufB);
    final_kernel<<<GROUPS, TB>>>(lw, lb, out);
}